// round 4
// baseline (speedup 1.0000x reference)
#include <cuda_runtime.h>
#include <math.h>

// ---------------- constants (from reference) ----------------
#define SPIN_LEN   100
#define TRAIN_LEN  200000
#define ML_C       2.9086f
#define SL_C       1.898f

#define CH      32          // output steps per thread (chunk)
#define WARMUP  512         // discarded convergence steps per thread
#define NW      (WARMUP + 32*CH)   // per-warp window length in steps = 1536
#define SKW(g)  ((g) + ((g) >> 5)) // smem skew: stride-32 reads -> conflict-free
#define SSZ     (SKW(NW-1) + 1)    // 1535 + 47 + 1 = 1583

#define STD_BLOCKS 128

// ---------------- device scratch (no allocations allowed) ----------------
__device__ double g_ps[STD_BLOCKS];
__device__ double g_pq[STD_BLOCKS];
__device__ float  g_obsstd;
__device__ float  g_P[8]; // thr, oo1, ol1, a1, k01, a2, k02

// ---------------- derived scalar parameters ----------------
__global__ void k_params(const float* cmean, const float* cstd,
                         const float* W_rom, const float* W_rlm, const float* W_rfm,
                         const float* b0_yom, const float* W_b1_yom,
                         const float* b0_ylm, const float* W_b2_ylm,
                         const float* theltaC)
{
    float mo = cmean[0], so = cstd[0];
    float eo = expf(W_rom[0]);
    float el = expf(W_rlm[0]);
    float ef = expf(W_rfm[0]);
    float den = eo + el + ef;
    g_P[0] = expf(theltaC[0]);      // thr
    g_P[1] = eo / den;              // oo1
    g_P[2] = el / den;              // ol1
    float a1 = W_b1_yom[0] / so;
    g_P[3] = a1;
    g_P[4] = b0_yom[0] - mo * a1;   // k01: arg_oo = fma(c, a1, k01)
    float a2 = W_b2_ylm[0] / SL_C;
    g_P[5] = a2;
    g_P[6] = b0_ylm[0] - ML_C * a2; // k02: arg_ol = fma(u2, a2, k02)
}

// ---------------- std(y_obs[100:200000], ddof=1) ----------------
__global__ void k_std1(const float* __restrict__ y)
{
    __shared__ double ss[256], sq[256];
    int tid = threadIdx.x;
    double a = 0.0, b = 0.0;
    for (int i = SPIN_LEN + blockIdx.x * 256 + tid; i < TRAIN_LEN; i += STD_BLOCKS * 256) {
        double v = (double)y[i];
        a += v; b += v * v;
    }
    ss[tid] = a; sq[tid] = b;
    __syncthreads();
    for (int s = 128; s > 0; s >>= 1) {
        if (tid < s) { ss[tid] += ss[tid + s]; sq[tid] += sq[tid + s]; }
        __syncthreads();
    }
    if (tid == 0) { g_ps[blockIdx.x] = ss[0]; g_pq[blockIdx.x] = sq[0]; }
}

__global__ void k_std2()
{
    __shared__ double ss[STD_BLOCKS], sq[STD_BLOCKS];
    int t = threadIdx.x;
    ss[t] = g_ps[t]; sq[t] = g_pq[t];
    __syncthreads();
    for (int s = STD_BLOCKS / 2; s > 0; s >>= 1) {
        if (t < s) { ss[t] += ss[t + s]; sq[t] += sq[t + s]; }
        __syncthreads();
    }
    if (t == 0) {
        double n = (double)(TRAIN_LEN - SPIN_LEN);
        double mean = ss[0] / n;
        double var  = (sq[0] - ss[0] * mean) / (n - 1.0);
        g_obsstd = (float)sqrt(var);
    }
}

// ---------------- main chunked-warmup scan ----------------
// 64 threads/block (2 warps). Each warp stages its x window [base-WARMUP, base+32*CH)
// into skewed smem; each lane owns one 32-step chunk, warms up 512 steps from c=0.
__global__ void __launch_bounds__(64)
k_scan(const float* __restrict__ x, float* __restrict__ out, int B)
{
    __shared__ float s1[2][SSZ];
    __shared__ float s2[2][SSZ];

    const int wl   = threadIdx.x >> 5;
    const int lane = threadIdx.x & 31;
    const int gw   = blockIdx.x * 2 + wl;          // global warp id
    const int warpStart = gw * (32 * CH) - WARMUP; // first step of window (may be <0)

    // cooperative coalesced fill of this warp's window
    for (int g = lane; g < NW; g += 32) {
        int i = warpStart + g;
        if (i >= 0) {
            float2 v = reinterpret_cast<const float2*>(x)[i];
            s1[wl][SKW(g)] = v.x;
            s2[wl][SKW(g)] = v.y;
        }
    }
    __syncthreads();

    const float thr = g_P[0], oo1 = g_P[1], ol1 = g_P[2];
    const float a1  = g_P[3], k01 = g_P[4];
    const float a2  = g_P[5], k02 = g_P[6];

    const int cs    = (gw * 32 + lane) * CH;  // this thread's chunk start
    const int gbase = lane * CH;              // lane's offset inside the window
    float c = 0.0f;

    // -------- warmup: converge c to the true trajectory (no outputs) --------
    #pragma unroll 4
    for (int k = 0; k < WARMUP; ++k) {
        const int g = gbase + k;
        const float u1 = s1[wl][SKW(g)];
        const float u2 = s2[wl][SKW(g)];
        if (cs - WARMUP + k >= 0) {
            float t   = u1 + c;
            float px  = fmaxf(t - thr, 0.0f);
            float oo  = __fdividef(oo1, 1.0f + __expf(-fmaf(c,  a1, k01)));
            float ol  = __fdividef(ol1, 1.0f + __expf(-fmaf(u2, a2, k02)));
            float olc = (c > 0.0f) ? fminf(ol, __fdividef(u2, c)) : ol;
            float f   = (1.0f - oo) - olc;
            c = fmaf(f, c, u1 - px);
        }
    }

    // -------- output phase: 32 steps, 10 streams --------
    #pragma unroll 4
    for (int k = 0; k < CH; ++k) {
        const int i = cs + k;
        const int g = gbase + WARMUP + k;
        const float u1 = s1[wl][SKW(g)];
        const float u2 = s2[wl][SKW(g)];

        float t   = u1 + c;
        float px  = fmaxf(t - thr, 0.0f);
        float oo  = __fdividef(oo1, 1.0f + __expf(-fmaf(c,  a1, k01)));
        float ol  = __fdividef(ol1, 1.0f + __expf(-fmaf(u2, a2, k02)));
        float olc = (c > 0.0f) ? fminf(ol, __fdividef(u2, c)) : ol;
        float f   = (1.0f - oo) - olc;
        float h   = fmaf(oo, c, px);
        float ib  = (u1 > 0.0f) ? __fdividef(px, u1) : 0.0f;

        out[          i] = h;        // h_n
        out[    B   + i] = c;        // c_n (pre-update)
        out[2 * B   + i] = ol * c;   // l_n
        out[3 * B   + i] = olc * c;  // lc_n
        out[4 * B   + i] = px;       // bp_n
        out[5 * B   + i] = ib;       // g_ib
        out[6 * B   + i] = oo;       // g_oo
        out[7 * B   + i] = ol;       // g_ol
        out[8 * B   + i] = olc;      // g_olc
        out[9 * B   + i] = f;        // g_f

        c = fmaf(f, c, u1 - px);
    }
}

// ---------------- h_nout (interleaved h,std) + obs_std streams ----------------
__global__ void k_fill(float* __restrict__ out, int B)
{
    int i = blockIdx.x * blockDim.x + threadIdx.x;
    if (i < B) {
        float stdv = g_obsstd;
        float h = out[i];
        reinterpret_cast<float2*>(out + 10 * (size_t)B)[i] = make_float2(h, stdv);
        out[12 * (size_t)B + i] = stdv;
    }
}

// ---------------- launch ----------------
extern "C" void kernel_launch(void* const* d_in, const int* in_sizes, int n_in,
                              void* d_out, int out_size)
{
    const float* x = (const float*)d_in[0];
    const float* y = (const float*)d_in[1];
    float* out = (float*)d_out;
    const int B = in_sizes[0] / 2;   // 262144

    k_params<<<1, 1>>>((const float*)d_in[2], (const float*)d_in[3],
                       (const float*)d_in[4], (const float*)d_in[5],
                       (const float*)d_in[6], (const float*)d_in[7],
                       (const float*)d_in[8], (const float*)d_in[9],
                       (const float*)d_in[10], (const float*)d_in[11]);

    k_std1<<<STD_BLOCKS, 256>>>(y);
    k_std2<<<1, STD_BLOCKS>>>();

    const int threads = B / CH;          // 8192 chunks
    const int blocks  = threads / 64;    // 128 blocks of 64 threads (2 warps)
    k_scan<<<blocks, 64>>>(x, out, B);

    k_fill<<<(B + 255) / 256, 256>>>(out, B);
}

// round 6
// speedup vs baseline: 2.8348x; 2.8348x over previous
#include <cuda_runtime.h>
#include <math.h>

// ---------------- constants (from reference) ----------------
#define SPIN_LEN   100
#define TRAIN_LEN  200000
#define ML_C       2.9086f
#define SL_C       1.898f
#define L2E        1.4426950408889634f

#define CH      8                   // output steps per chain
#define IL      2                   // interleaved chains per thread
#define WARM    192                 // discarded convergence steps per chain
#define OUTW    (32 * IL * CH)      // 512 output steps per warp
#define NW      (WARM + OUTW)       // 704-step input window per warp
#define SK(a)   ((a) + ((a) >> 5))  // smem skew -> conflict-free strided access
#define SWIN    (SK(NW - 1) + 1)    // 725
#define SOUT    (SK(OUTW - 1) + 1)  // 527

#define STD_BLOCKS 128

// ---------------- device scratch ----------------
__device__ double g_ps[STD_BLOCKS];
__device__ double g_pq[STD_BLOCKS];
__device__ float  g_obsstd;
__device__ float  g_P[8]; // thr, oo1, ol1, a1n, k01n, a2n, k02n

__device__ __forceinline__ float ex2f(float x) { float y; asm("ex2.approx.f32 %0, %1;" : "=f"(y) : "f"(x)); return y; }
__device__ __forceinline__ float rcpf(float x) { float y; asm("rcp.approx.f32 %0, %1;" : "=f"(y) : "f"(x)); return y; }

// ---------------- derived scalar parameters ----------------
__global__ void k_params(const float* cmean, const float* cstd,
                         const float* W_rom, const float* W_rlm, const float* W_rfm,
                         const float* b0_yom, const float* W_b1_yom,
                         const float* b0_ylm, const float* W_b2_ylm,
                         const float* theltaC)
{
    float mo = cmean[0], so = cstd[0];
    float eo = expf(W_rom[0]);
    float el = expf(W_rlm[0]);
    float ef = expf(W_rfm[0]);
    float den = eo + el + ef;
    g_P[0] = expf(theltaC[0]);                 // thr
    g_P[1] = eo / den;                         // oo1
    g_P[2] = el / den;                         // ol1
    float a1 = W_b1_yom[0] / so;
    float k1 = b0_yom[0] - mo * a1;
    g_P[3] = -a1 * L2E;                        // a1n:  exp(-z) = ex2(fma(c, a1n, k01n))
    g_P[4] = -k1 * L2E;                        // k01n
    float a2 = W_b2_ylm[0] / SL_C;
    float k2 = b0_ylm[0] - ML_C * a2;
    g_P[5] = -a2 * L2E;                        // a2n
    g_P[6] = -k2 * L2E;                        // k02n
}

// ---------------- std(y_obs[100:200000], ddof=1) ----------------
__global__ void k_std1(const float* __restrict__ y)
{
    __shared__ double ss[256], sq[256];
    int tid = threadIdx.x;
    double a = 0.0, b = 0.0;
    for (int i = SPIN_LEN + blockIdx.x * 256 + tid; i < TRAIN_LEN; i += STD_BLOCKS * 256) {
        double v = (double)y[i];
        a += v; b += v * v;
    }
    ss[tid] = a; sq[tid] = b;
    __syncthreads();
    for (int s = 128; s > 0; s >>= 1) {
        if (tid < s) { ss[tid] += ss[tid + s]; sq[tid] += sq[tid + s]; }
        __syncthreads();
    }
    if (tid == 0) { g_ps[blockIdx.x] = ss[0]; g_pq[blockIdx.x] = sq[0]; }
}

__global__ void k_std2()
{
    __shared__ double ss[STD_BLOCKS], sq[STD_BLOCKS];
    int t = threadIdx.x;
    ss[t] = g_ps[t]; sq[t] = g_pq[t];
    __syncthreads();
    for (int s = STD_BLOCKS / 2; s > 0; s >>= 1) {
        if (t < s) { ss[t] += ss[t + s]; sq[t] += sq[t + s]; }
        __syncthreads();
    }
    if (t == 0) {
        double n = (double)(TRAIN_LEN - SPIN_LEN);
        double mean = ss[0] / n;
        double var  = (sq[0] - ss[0] * mean) / (n - 1.0);
        g_obsstd = (float)sqrt(var);
    }
}

// ---------------- main chunked-warmup scan ----------------
// 1 warp per block. Each warp emits 512 consecutive output steps; each thread
// runs 2 interleaved chains: WARM discarded warmup steps over the window range
// [chain_off, chain_off+WARM) followed by CH emitted steps over
// [chain_off+WARM, chain_off+WARM+CH).  (R5 bug: output phase omitted +WARM.)
__global__ void __launch_bounds__(32)
k_scan(const float* __restrict__ x, float* __restrict__ out, int B)
{
    __shared__ float su1[SWIN], su2[SWIN], sol[SWIN];
    __shared__ float ob[10][SOUT];

    const int lane   = threadIdx.x;
    const int base   = blockIdx.x * OUTW;   // first emitted global step
    const int wstart = base - WARM;         // window start (may be < 0)

    const float thr = g_P[0], oo1 = g_P[1], ol1 = g_P[2];
    const float a1n = g_P[3], k01n = g_P[4];
    const float a2n = g_P[5], k02n = g_P[6];

    // ---- stage window: coalesced load + precompute ol(u2) ----
    // Negative steps zero-filled: with u1=u2=ol=0 the recurrence keeps c==0
    // exactly (px=0 since thr>0, olcc=min(0,0)=0, ooc=oo*0=0), so chunks whose
    // warmup crosses step 0 are computed EXACTLY from c0=0.
    for (int g = lane; g < NW; g += 32) {
        int i = wstart + g;
        float u1 = 0.0f, u2 = 0.0f, ol = 0.0f;
        if (i >= 0) {
            float2 v = reinterpret_cast<const float2*>(x)[i];
            u1 = v.x; u2 = v.y;
            ol = ol1 * rcpf(1.0f + ex2f(fmaf(u2, a2n, k02n)));
        }
        su1[SK(g)] = u1; su2[SK(g)] = u2; sol[SK(g)] = ol;
    }
    __syncwarp();

    const int g0 = lane * CH;          // chain 0 window offset (warmup start)
    const int g1 = (lane + 32) * CH;   // chain 1 window offset
    float c0 = 0.0f, c1 = 0.0f;

    // ---- warmup: two independent chains interleaved (ILP=2), divide-free ----
    // identity: olc*c == min(ol*c, u2)  (u2>=0; for c<=0 both sides = ol*c/0)
    #pragma unroll 4
    for (int k = 0; k < WARM; ++k) {
        {
            float u1 = su1[SK(g0 + k)], u2 = su2[SK(g0 + k)], ol = sol[SK(g0 + k)];
            float s    = rcpf(1.0f + ex2f(fmaf(c0, a1n, k01n)));
            float ooc  = oo1 * s * c0;
            float olcc = fminf(ol * c0, u2);
            float px   = fmaxf(u1 + c0 - thr, 0.0f);
            c0 = ((c0 - ooc) - olcc) + (u1 - px);
        }
        {
            float u1 = su1[SK(g1 + k)], u2 = su2[SK(g1 + k)], ol = sol[SK(g1 + k)];
            float s    = rcpf(1.0f + ex2f(fmaf(c1, a1n, k01n)));
            float ooc  = oo1 * s * c1;
            float olcc = fminf(ol * c1, u2);
            float px   = fmaxf(u1 + c1 - thr, 0.0f);
            c1 = ((c1 - ooc) - olcc) + (u1 - px);
        }
    }

    // ---- output phase: CH steps per chain, results into smem transpose buf ----
    #pragma unroll
    for (int k = 0; k < CH; ++k) {
        #pragma unroll
        for (int j = 0; j < IL; ++j) {
            float& c = j ? c1 : c0;
            const int g = (j ? g1 : g0) + WARM + k;            // <<< fixed: +WARM
            const int t = (j ? (lane + 32) : lane) * CH + k;

            float u1 = su1[SK(g)], u2 = su2[SK(g)], ol = sol[SK(g)];
            float s    = rcpf(1.0f + ex2f(fmaf(c, a1n, k01n)));
            float oo   = oo1 * s;
            float ooc  = oo * c;
            float olc  = (c > 0.0f) ? fminf(ol, u2 * rcpf(c)) : ol;
            float olcc = olc * c;
            float px   = fmaxf(u1 + c - thr, 0.0f);
            float ib   = (u1 > 0.0f) ? px * rcpf(u1) : 0.0f;
            float f    = (1.0f - oo) - olc;

            ob[0][SK(t)] = ooc + px;   // h_n
            ob[1][SK(t)] = c;          // c_n (pre-update)
            ob[2][SK(t)] = ol * c;     // l_n
            ob[3][SK(t)] = olcc;       // lc_n
            ob[4][SK(t)] = px;         // bp_n
            ob[5][SK(t)] = ib;         // g_ib
            ob[6][SK(t)] = oo;         // g_oo
            ob[7][SK(t)] = ol;         // g_ol
            ob[8][SK(t)] = olc;        // g_olc
            ob[9][SK(t)] = f;          // g_f

            c = ((c - ooc) - olcc) + (u1 - px);
        }
    }
    __syncwarp();

    // ---- coalesced flush (also produces h_nout and obs_std streams) ----
    #pragma unroll
    for (int st = 0; st < 10; ++st) {
        #pragma unroll
        for (int t = lane; t < OUTW; t += 32)
            out[(size_t)st * B + base + t] = ob[st][SK(t)];
    }
    const float stdv = g_obsstd;
    float2* o2 = reinterpret_cast<float2*>(out + 10 * (size_t)B);
    #pragma unroll
    for (int t = lane; t < OUTW; t += 32) {
        o2[base + t] = make_float2(ob[0][SK(t)], stdv);   // h_nout = [h, std]
        out[12 * (size_t)B + base + t] = stdv;            // obs_std
    }
}

// ---------------- launch ----------------
extern "C" void kernel_launch(void* const* d_in, const int* in_sizes, int n_in,
                              void* d_out, int out_size)
{
    const float* x = (const float*)d_in[0];
    const float* y = (const float*)d_in[1];
    float* out = (float*)d_out;
    const int B = in_sizes[0] / 2;   // 262144

    k_params<<<1, 1>>>((const float*)d_in[2], (const float*)d_in[3],
                       (const float*)d_in[4], (const float*)d_in[5],
                       (const float*)d_in[6], (const float*)d_in[7],
                       (const float*)d_in[8], (const float*)d_in[9],
                       (const float*)d_in[10], (const float*)d_in[11]);

    k_std1<<<STD_BLOCKS, 256>>>(y);
    k_std2<<<1, STD_BLOCKS>>>();

    const int blocks = B / OUTW;     // 512 one-warp blocks
    k_scan<<<blocks, 32>>>(x, out, B);
}

// round 7
// speedup vs baseline: 3.7234x; 1.3135x over previous
#include <cuda_runtime.h>
#include <math.h>

// ---------------- constants (from reference) ----------------
#define SPIN_LEN   100
#define TRAIN_LEN  200000
#define ML_C       2.9086f
#define SL_C       1.898f
#define L2E        1.4426950408889634f

#define CH      8                    // output steps per chain (must be 8: affine-addr trick)
#define WARM    128                  // discarded convergence steps (multiple of 8)
#define OUTW    (64 * CH)            // 512 output steps per warp (64 chains: 2/thread)
#define NW      (WARM + OUTW)        // 640-step input window per warp
#define SK4(g)  ((g) + ((g) >> 3))   // float4 skew: lane-stride-8 LDS.128 conflict-free
#define SWIN4   (SK4(NW - 1) + 1)    // 719
#define SKO(t)  ((t) + ((t) >> 5))   // float skew for output buffer
#define SOUT    (SKO(OUTW - 1) + 1)  // 527

#define STD_BLOCKS 128

// ---------------- device scratch ----------------
__device__ double g_ps[STD_BLOCKS];
__device__ double g_pq[STD_BLOCKS];
__device__ float  g_obsstd;
__device__ float  g_P[8]; // thr, oo1, ol1, a1n, k01n, a2n, k02n

__device__ __forceinline__ float ex2f(float x) { float y; asm("ex2.approx.f32 %0, %1;" : "=f"(y) : "f"(x)); return y; }
__device__ __forceinline__ float rcpf(float x) { float y; asm("rcp.approx.f32 %0, %1;" : "=f"(y) : "f"(x)); return y; }

// ---------------- std(y_obs[100:200000], ddof=1) ----------------
__global__ void k_std1(const float* __restrict__ y)
{
    __shared__ double ss[256], sq[256];
    int tid = threadIdx.x;
    double a = 0.0, b = 0.0;
    for (int i = SPIN_LEN + blockIdx.x * 256 + tid; i < TRAIN_LEN; i += STD_BLOCKS * 256) {
        double v = (double)y[i];
        a += v; b += v * v;
    }
    ss[tid] = a; sq[tid] = b;
    __syncthreads();
    for (int s = 128; s > 0; s >>= 1) {
        if (tid < s) { ss[tid] += ss[tid + s]; sq[tid] += sq[tid + s]; }
        __syncthreads();
    }
    if (tid == 0) { g_ps[blockIdx.x] = ss[0]; g_pq[blockIdx.x] = sq[0]; }
}

// final std reduction + derived scalar parameters (merged)
__global__ void k_std2(const float* cmean, const float* cstd,
                       const float* W_rom, const float* W_rlm, const float* W_rfm,
                       const float* b0_yom, const float* W_b1_yom,
                       const float* b0_ylm, const float* W_b2_ylm,
                       const float* theltaC)
{
    __shared__ double ss[STD_BLOCKS], sq[STD_BLOCKS];
    int t = threadIdx.x;
    ss[t] = g_ps[t]; sq[t] = g_pq[t];
    __syncthreads();
    for (int s = STD_BLOCKS / 2; s > 0; s >>= 1) {
        if (t < s) { ss[t] += ss[t + s]; sq[t] += sq[t + s]; }
        __syncthreads();
    }
    if (t == 0) {
        double n = (double)(TRAIN_LEN - SPIN_LEN);
        double mean = ss[0] / n;
        double var  = (sq[0] - ss[0] * mean) / (n - 1.0);
        g_obsstd = (float)sqrt(var);
    } else if (t == 1) {
        float mo = cmean[0], so = cstd[0];
        float eo = expf(W_rom[0]);
        float el = expf(W_rlm[0]);
        float ef = expf(W_rfm[0]);
        float den = eo + el + ef;
        g_P[0] = expf(theltaC[0]);                 // thr
        g_P[1] = eo / den;                         // oo1
        g_P[2] = el / den;                         // ol1
        float a1 = W_b1_yom[0] / so;
        float k1 = b0_yom[0] - mo * a1;
        g_P[3] = -a1 * L2E;                        // a1n: exp(-z)=ex2(fma(c,a1n,k01n))
        g_P[4] = -k1 * L2E;                        // k01n
        float a2 = W_b2_ylm[0] / SL_C;
        float k2 = b0_ylm[0] - ML_C * a2;
        g_P[5] = -a2 * L2E;                        // a2n
        g_P[6] = -k2 * L2E;                        // k02n
    }
}

// ---------------- main chunked-warmup scan ----------------
// 1 warp per block, 512 output steps per warp, 2 chains per thread.
// Inputs (u1,u2) + precomputed ol(u2) staged as float4 in skewed smem;
// outputs transposed through skewed smem, flushed coalesced.
__global__ void __launch_bounds__(32)
k_scan(const float* __restrict__ x, float* __restrict__ out, int B)
{
    __shared__ float4 sw[SWIN4];
    __shared__ float  ob[10 * SOUT];

    const int lane   = threadIdx.x;
    const int base   = blockIdx.x * OUTW;   // first emitted global step
    const int wstart = base - WARM;         // window start (may be < 0)

    const float thr = g_P[0], oo1 = g_P[1], ol1 = g_P[2];
    const float a1n = g_P[3], k01n = g_P[4];
    const float a2n = g_P[5], k02n = g_P[6];

    // ---- stage window: coalesced load + precompute ol(u2) ----
    // Zero-fill for steps < 0 keeps c == 0 exactly through them
    // (m = min(0, thr) = 0, olcc = 0, ooc = 0).
    #pragma unroll
    for (int g = lane; g < NW; g += 32) {
        int i = wstart + g;
        float u1 = 0.0f, u2 = 0.0f, ol = 0.0f;
        if (i >= 0) {
            float2 v = reinterpret_cast<const float2*>(x)[i];
            u1 = v.x; u2 = v.y;
            ol = ol1 * rcpf(1.0f + ex2f(fmaf(u2, a2n, k02n)));
        }
        sw[SK4(g)] = make_float4(u1, u2, ol, 0.0f);
    }
    __syncwarp();

    const int g0 = lane * CH;           // chain 0 window start (multiple of 8)
    const int g1 = (lane + 32) * CH;    // chain 1 window start (multiple of 8)
    float c0 = 0.0f, c1 = 0.0f;

    // ---- warmup: 2 interleaved chains, divide-free, affine smem addressing ----
    // step: m = min(u1, thr-c); olcc = min(ol*c, u2); A = (c - olcc) + m;
    //       c' = fma(-oo1*c, 1/(1+2^(c*a1n+k01n)), A)
    for (int k0 = 0; k0 < WARM; k0 += 8) {
        // g0+k0, g1+k0 are multiples of 8 -> (g+k)>>3 constant over k in [0,8)
        const float4* p0 = &sw[SK4(g0 + k0)];
        const float4* p1 = &sw[SK4(g1 + k0)];
        #pragma unroll
        for (int k = 0; k < 8; ++k) {
            {
                float4 v = p0[k];
                float e    = ex2f(fmaf(c0, a1n, k01n));
                float s    = rcpf(1.0f + e);
                float t    = oo1 * c0;
                float olcc = fminf(v.z * c0, v.y);
                float m    = fminf(v.x, thr - c0);
                float A    = (c0 - olcc) + m;
                c0 = fmaf(-t, s, A);
            }
            {
                float4 v = p1[k];
                float e    = ex2f(fmaf(c1, a1n, k01n));
                float s    = rcpf(1.0f + e);
                float t    = oo1 * c1;
                float olcc = fminf(v.z * c1, v.y);
                float m    = fminf(v.x, thr - c1);
                float A    = (c1 - olcc) + m;
                c1 = fmaf(-t, s, A);
            }
        }
    }

    // ---- output phase: 8 steps per chain, full outputs into smem transpose ----
    // t0 = 8*lane + k : (t0>>5) = lane>>2 is k-invariant -> affine store base
    const int sb0 = 8 * lane + (lane >> 2);                     // SKO(8*lane)
    const int sb1 = 8 * (lane + 32) + ((lane + 32) >> 2);       // SKO(8*(lane+32))
    {
        const float4* p0 = &sw[SK4(g0 + WARM)];
        const float4* p1 = &sw[SK4(g1 + WARM)];
        #pragma unroll
        for (int k = 0; k < CH; ++k) {
            #pragma unroll
            for (int j = 0; j < 2; ++j) {
                float c = j ? c1 : c0;
                float4 v = j ? p1[k] : p0[k];
                float* q = &ob[(j ? sb1 : sb0) + k];

                float s    = rcpf(1.0f + ex2f(fmaf(c, a1n, k01n)));
                float oo   = oo1 * s;
                float ooc  = oo * c;
                float olc  = (c > 0.0f) ? fminf(v.z, v.y * rcpf(c)) : v.z;
                float olcc = olc * c;
                float px   = fmaxf(v.x + c - thr, 0.0f);
                float ib   = (v.x > 0.0f) ? px * rcpf(v.x) : 0.0f;
                float f    = (1.0f - oo) - olc;

                q[0 * SOUT] = ooc + px;   // h_n
                q[1 * SOUT] = c;          // c_n (pre-update)
                q[2 * SOUT] = v.z * c;    // l_n
                q[3 * SOUT] = olcc;       // lc_n
                q[4 * SOUT] = px;         // bp_n
                q[5 * SOUT] = ib;         // g_ib
                q[6 * SOUT] = oo;         // g_oo
                q[7 * SOUT] = v.z;        // g_ol
                q[8 * SOUT] = olc;        // g_olc
                q[9 * SOUT] = f;          // g_f

                c = ((c - ooc) - olcc) + (v.x - px);
                if (j) c1 = c; else c0 = c;
            }
        }
    }
    __syncwarp();

    // ---- coalesced flush (also produces h_nout and obs_std streams) ----
    #pragma unroll
    for (int st = 0; st < 10; ++st) {
        #pragma unroll
        for (int m = 0; m < OUTW / 32; ++m) {
            int t = lane + 32 * m;
            out[(size_t)st * B + base + t] = ob[st * SOUT + t + m]; // SKO(t)=t+m
        }
    }
    const float stdv = g_obsstd;
    float2* o2 = reinterpret_cast<float2*>(out + 10 * (size_t)B);
    #pragma unroll
    for (int m = 0; m < OUTW / 32; ++m) {
        int t = lane + 32 * m;
        o2[base + t] = make_float2(ob[t + m], stdv);   // h_nout = [h, std]
        out[12 * (size_t)B + base + t] = stdv;         // obs_std
    }
}

// ---------------- launch ----------------
extern "C" void kernel_launch(void* const* d_in, const int* in_sizes, int n_in,
                              void* d_out, int out_size)
{
    const float* x = (const float*)d_in[0];
    const float* y = (const float*)d_in[1];
    float* out = (float*)d_out;
    const int B = in_sizes[0] / 2;   // 262144

    k_std1<<<STD_BLOCKS, 256>>>(y);
    k_std2<<<1, STD_BLOCKS>>>((const float*)d_in[2], (const float*)d_in[3],
                              (const float*)d_in[4], (const float*)d_in[5],
                              (const float*)d_in[6], (const float*)d_in[7],
                              (const float*)d_in[8], (const float*)d_in[9],
                              (const float*)d_in[10], (const float*)d_in[11]);

    const int blocks = B / OUTW;     // 512 one-warp blocks
    k_scan<<<blocks, 32>>>(x, out, B);
}